// round 10
// baseline (speedup 1.0000x reference)
#include <cuda_runtime.h>
#include <cuda_bf16.h>

#define BATCH 1024
#define SEQ   512
#define HID   64
#define GATES 256
#define NR    8
#define NCTA  (BATCH / NR)   // 128
#define NTHR  512            // 16 warps: 8 heavy (gates2) + 8 light (gates1)

typedef unsigned long long ull;

struct __align__(16) Smem {
    // Weight layout: W[k][col], col = j*4 + hq (cell j, gate hq: 0=i,1=f,2=g,3=o)
    float W1[HID][GATES];          //  64 KB (W_hh1)
    float W2[2 * HID][GATES];      // 128 KB ([W_ih2 ; W_hh2])
    float hb[2 * HID][NR];         //   4 KB [k][row]; k<64: h1, k>=64: h2
    ulonglong2 pexA[4][3][64];     //  12 KB [pair][slot][cell] gates (i,f) — L2 only
    ulonglong2 pexB[4][3][64];     //  12 KB gates (g,o)
    float wih1v[GATES];
    float b1v[GATES];
    float b2v[GATES];
    float wlin[HID];
    float xs[2][NR];
    float outp[4][2][2];           // [pair][hh][row-in-pair]
    float blin;
};   // ~223.5 KB

__device__ __forceinline__ ull pk2(float lo, float hi) {
    ull r; asm("mov.b64 %0, {%1, %2};" : "=l"(r) : "f"(lo), "f"(hi)); return r;
}
__device__ __forceinline__ void unpk(ull v, float& lo, float& hi) {
    asm("mov.b64 {%0, %1}, %2;" : "=f"(lo), "=f"(hi) : "l"(v));
}
__device__ __forceinline__ void fma2(ull& d, ull a, ull b) {
    asm("fma.rn.f32x2 %0, %1, %2, %0;" : "+l"(d) : "l"(a), "l"(b));
}
__device__ __forceinline__ ull add2(ull a, ull b) {
    ull d; asm("add.rn.f32x2 %0, %1, %2;" : "=l"(d) : "l"(a), "l"(b)); return d;
}

// MUFU.TANH (sm_75+), rel err ~2e-5
__device__ __forceinline__ float tanh_fast(float x) {
    float r; asm("tanh.approx.f32 %0, %1;" : "=f"(r) : "f"(x)); return r;
}
__device__ __forceinline__ float sigf(float v) {
    return fmaf(0.5f, tanh_fast(0.5f * v), 0.5f);
}

// 8 k-steps: acc[q][p] += h[k][rows 2p,2p+1] * w[k][cell*4+q]
__device__ __forceinline__ void gemm8(const float* __restrict__ wp,
                                      const float* __restrict__ hp,
                                      ull acc[4][4]) {
#pragma unroll
    for (int kk = 0; kk < 8; kk++) {
        float4 wv = *reinterpret_cast<const float4*>(wp + kk * GATES);
        ulonglong2 hA = *reinterpret_cast<const ulonglong2*>(hp + kk * 8);
        ulonglong2 hB = *reinterpret_cast<const ulonglong2*>(hp + kk * 8 + 4);
        ull w;
        w = pk2(wv.x, wv.x);
        fma2(acc[0][0], hA.x, w); fma2(acc[0][1], hA.y, w);
        fma2(acc[0][2], hB.x, w); fma2(acc[0][3], hB.y, w);
        w = pk2(wv.y, wv.y);
        fma2(acc[1][0], hA.x, w); fma2(acc[1][1], hA.y, w);
        fma2(acc[1][2], hB.x, w); fma2(acc[1][3], hB.y, w);
        w = pk2(wv.z, wv.z);
        fma2(acc[2][0], hA.x, w); fma2(acc[2][1], hA.y, w);
        fma2(acc[2][2], hB.x, w); fma2(acc[2][3], hB.y, w);
        w = pk2(wv.w, wv.w);
        fma2(acc[3][0], hA.x, w); fma2(acc[3][1], hA.y, w);
        fma2(acc[3][2], hB.x, w); fma2(acc[3][3], hB.y, w);
    }
}

// LSTM cell for a packed row-pair: gates (i,f,g,o) each f32x2 -> h f32x2.
__device__ __forceinline__ ull act2(ull ai, ull af, ull ag, ull ao,
                                    float& ca, float& cb) {
    float i0, i1, f0, f1, g0, g1, o0, o1;
    unpk(ai, i0, i1); unpk(af, f0, f1);
    unpk(ag, g0, g1); unpk(ao, o0, o1);
    float cA = sigf(f0) * ca + sigf(i0) * tanh_fast(g0);
    float cB = sigf(f1) * cb + sigf(i1) * tanh_fast(g1);
    ca = cA; cb = cB;
    return pk2(sigf(o0) * tanh_fast(cA), sigf(o1) * tanh_fast(cB));
}

// Extract this group's row-pair with static indices (avoid local-mem demotion).
__device__ __forceinline__ void own_pair(const ull acc[4][4], int g,
                                         ull& ai, ull& af, ull& ag, ull& ao) {
    ai = 0; af = 0; ag = 0; ao = 0;
#pragma unroll
    for (int p = 0; p < 4; p++)
        if (p == g) { ai = acc[0][p]; af = acc[1][p]; ag = acc[2][p]; ao = acc[3][p]; }
}

__global__ void __launch_bounds__(NTHR, 1)
lstm_persistent_kernel(const float* __restrict__ x,
                       const float* __restrict__ Wih1, const float* __restrict__ Whh1,
                       const float* __restrict__ bih1, const float* __restrict__ bhh1,
                       const float* __restrict__ Wih2, const float* __restrict__ Whh2,
                       const float* __restrict__ bih2, const float* __restrict__ bhh2,
                       const float* __restrict__ Wlin, const float* __restrict__ blin,
                       float* __restrict__ out) {
    extern __shared__ char smem_raw[];
    Smem& sm = *reinterpret_cast<Smem*>(smem_raw);

    const int tid  = threadIdx.x;
    const int wid  = tid >> 5;
    const int lane = tid & 31;
    const int row0 = blockIdx.x * NR;

    // ---- one-time staging ----
    for (int i = tid; i < GATES * HID; i += NTHR) {
        int gsrc = i >> 6, k = i & 63;
        int col = (gsrc & 63) * 4 + (gsrc >> 6);
        sm.W1[k][col]      = Whh1[i];
        sm.W2[k][col]      = Wih2[i];
        sm.W2[64 + k][col] = Whh2[i];
    }
    for (int gsrc = tid; gsrc < GATES; gsrc += NTHR) {
        int col = (gsrc & 63) * 4 + (gsrc >> 6);
        sm.wih1v[col] = Wih1[gsrc];
        sm.b1v[col]   = bih1[gsrc] + bhh1[gsrc];
        sm.b2v[col]   = bih2[gsrc] + bhh2[gsrc];
    }
    if (tid < HID) sm.wlin[tid] = Wlin[tid];
    if (tid == 0)  sm.blin = blin[0];
    for (int i = tid; i < 2 * HID * NR; i += NTHR)
        reinterpret_cast<float*>(sm.hb)[i] = 0.0f;
    if (tid < NR) {
        sm.xs[1][tid] = x[(row0 + tid) * SEQ + 0];  // x(0) for prologue
        sm.xs[0][tid] = x[(row0 + tid) * SEQ + 1];  // x(1) for GEMM(0)
    }
    __syncthreads();

    const bool isL1 = (wid >= 8);
    // L2 (heavy) mapping: group g (k-slice 32, owns row-pair g), cell half hh
    const int g    = (wid >> 1) & 3;
    const int hh   = wid & 1;
    // L1 (light) mapping: warp owns 8 cells, lane-octet = k-quarter kq (16 k)
    const int kq   = lane >> 3;
    const int pr   = ((kq & 1) << 1) | (kq >> 1);    // owned row-pair after reduce
    const int j    = isL1 ? ((wid - 8) * 8 + (lane & 7)) : (hh * 32 + lane);
    const int c4   = j * 4;

    // c-state: every lane holds c for ONE row-pair of its cell
    float cs0 = 0.f, cs1 = 0.f;
    const float wl = sm.wlin[j];

    // ---- prologue: gates1(0) = b1 + x(0)*wih1 (h1(-1)=0), L1 warps, pair pr ----
    if (isL1) {
        float4 wiv = *reinterpret_cast<const float4*>(&sm.wih1v[c4]);
        float4 bv  = *reinterpret_cast<const float4*>(&sm.b1v[c4]);
        ull xq = *reinterpret_cast<const ull*>(&sm.xs[1][2 * pr]);
        float wivf[4] = {wiv.x, wiv.y, wiv.z, wiv.w};
        float bvf[4]  = {bv.x, bv.y, bv.z, bv.w};
        ull gp[4];
#pragma unroll
        for (int q = 0; q < 4; q++) {
            gp[q] = pk2(bvf[q], bvf[q]);
            fma2(gp[q], xq, pk2(wivf[q], wivf[q]));
        }
        ull hp = act2(gp[0], gp[1], gp[2], gp[3], cs0, cs1);
        *reinterpret_cast<ull*>(&sm.hb[j][2 * pr]) = hp;
    }
    __syncthreads();

    for (int t = 0; t < SEQ; t++) {
        // finalize out[t-1]
        if (t > 0 && tid < NR) {
            out[(row0 + tid) * SEQ + (t - 1)] =
                sm.blin + sm.outp[tid >> 1][0][tid & 1] + sm.outp[tid >> 1][1][tid & 1];
        }

        // ===== GEMM phase =====
        ull acc[4][4];
        {
            if (!isL1 && g == 0) {
                float4 bv = *reinterpret_cast<const float4*>(&sm.b2v[c4]);
                ull b;
                b = pk2(bv.x, bv.x); acc[0][0]=b; acc[0][1]=b; acc[0][2]=b; acc[0][3]=b;
                b = pk2(bv.y, bv.y); acc[1][0]=b; acc[1][1]=b; acc[1][2]=b; acc[1][3]=b;
                b = pk2(bv.z, bv.z); acc[2][0]=b; acc[2][1]=b; acc[2][2]=b; acc[2][3]=b;
                b = pk2(bv.w, bv.w); acc[3][0]=b; acc[3][1]=b; acc[3][2]=b; acc[3][3]=b;
            } else if (isL1 && kq == 0) {
                float4 wiv = *reinterpret_cast<const float4*>(&sm.wih1v[c4]);
                float4 bv  = *reinterpret_cast<const float4*>(&sm.b1v[c4]);
                const float* xp = sm.xs[t & 1];   // x(t+1)
                ulonglong2 xA = *reinterpret_cast<const ulonglong2*>(xp);
                ulonglong2 xB = *reinterpret_cast<const ulonglong2*>(xp + 4);
                float wivf[4] = {wiv.x, wiv.y, wiv.z, wiv.w};
                float bvf[4]  = {bv.x, bv.y, bv.z, bv.w};
#pragma unroll
                for (int q = 0; q < 4; q++) {
                    ull b = pk2(bvf[q], bvf[q]);
                    ull w = pk2(wivf[q], wivf[q]);
                    acc[q][0] = b; fma2(acc[q][0], xA.x, w);
                    acc[q][1] = b; fma2(acc[q][1], xA.y, w);
                    acc[q][2] = b; fma2(acc[q][2], xB.x, w);
                    acc[q][3] = b; fma2(acc[q][3], xB.y, w);
                }
            } else {
#pragma unroll
                for (int q = 0; q < 4; q++)
#pragma unroll
                    for (int p = 0; p < 4; p++) acc[q][p] = 0ull;
            }
            if (!isL1) {   // gates2(t): 32-k slice of W2 over [h1;h2]
                const float* wp = &sm.W2[g * 32][c4];
                const float* hp = &sm.hb[g * 32][0];
#pragma unroll 1
                for (int kb = 0; kb < 4; kb++) {
                    gemm8(wp, hp, acc);
                    wp += 8 * GATES; hp += 8 * NR;
                }
            } else {       // gates1(t+1): 16-k slice (lane-octet kq) of W1 over h1(t)
                const float* wp = &sm.W1[kq * 16][c4];
                const float* hp = &sm.hb[kq * 16][0];
                gemm8(wp, hp, acc);
                gemm8(wp + 8 * GATES, hp + 8 * NR, acc);
            }
        }

        // ship L2 partials (L1 reduces purely via shuffle)
        if (!isL1) {
#pragma unroll
            for (int p = 0; p < 4; p++)
                if (p != g) {
                    int s = (g < p) ? g : g - 1;
                    sm.pexA[p][s][j] = make_ulonglong2(acc[0][p], acc[1][p]);
                    sm.pexB[p][s][j] = make_ulonglong2(acc[2][p], acc[3][p]);
                }
        }
        __syncthreads();

        // ===== ACT phase =====
        if (!isL1) {
            // reduce 4-way over SMEM, activate pair g -> h2(t)
            ull ai, af, ag, ao;
            own_pair(acc, g, ai, af, ag, ao);
#pragma unroll
            for (int s = 0; s < 3; s++) {
                ulonglong2 ra = sm.pexA[g][s][j];
                ulonglong2 rb = sm.pexB[g][s][j];
                ai = add2(ai, ra.x); af = add2(af, ra.y);
                ag = add2(ag, rb.x); ao = add2(ao, rb.y);
            }
            ull h2p = act2(ai, af, ag, ao, cs0, cs1);
            *reinterpret_cast<ull*>(&sm.hb[64 + j][2 * g]) = h2p;

            // out(t) partials: rows 2g,2g+1, reduced over this warp's 32 cells
            float h0, h1;
            unpk(h2p, h0, h1);
            float p0 = wl * h0, p1 = wl * h1;
#pragma unroll
            for (int off = 16; off > 0; off >>= 1) {
                p0 += __shfl_xor_sync(0xffffffffu, p0, off);
                p1 += __shfl_xor_sync(0xffffffffu, p1, off);
            }
            if (lane == 0) {
                sm.outp[g][hh][0] = p0;
                sm.outp[g][hh][1] = p1;
            }
        } else {
            // intra-warp 4-way k-reduce: xor-8 then xor-16; activate pair pr
            const bool low = ((kq & 1) == 0);   // keeps pairs {0,1} in round 1
            ull kp0[4], kp1[4];
#pragma unroll
            for (int q = 0; q < 4; q++) {
                ull s0 = low ? acc[q][2] : acc[q][0];
                ull s1 = low ? acc[q][3] : acc[q][1];
                ull r0 = __shfl_xor_sync(0xffffffffu, s0, 8);
                ull r1 = __shfl_xor_sync(0xffffffffu, s1, 8);
                ull k0 = low ? acc[q][0] : acc[q][2];
                ull k1 = low ? acc[q][1] : acc[q][3];
                kp0[q] = add2(k0, r0);   // pair 2*(kq&1)
                kp1[q] = add2(k1, r1);   // pair 2*(kq&1)+1
            }
            const bool hi0 = (kq < 2);          // keeps kp0 in round 2
            ull gp[4];
#pragma unroll
            for (int q = 0; q < 4; q++) {
                ull s = hi0 ? kp1[q] : kp0[q];
                ull r = __shfl_xor_sync(0xffffffffu, s, 16);
                ull k = hi0 ? kp0[q] : kp1[q];
                gp[q] = add2(k, r);             // full-k gates for pair pr
            }
            ull h1p = act2(gp[0], gp[1], gp[2], gp[3], cs0, cs1);
            *reinterpret_cast<ull*>(&sm.hb[j][2 * pr]) = h1p;
        }
        // prefetch x(t+2)
        if (tid < NR && (t + 2) < SEQ)
            sm.xs[(t + 1) & 1][tid] = x[(row0 + tid) * SEQ + t + 2];
        __syncthreads();
    }

    if (tid < NR) {
        out[(row0 + tid) * SEQ + (SEQ - 1)] =
            sm.blin + sm.outp[tid >> 1][0][tid & 1] + sm.outp[tid >> 1][1][tid & 1];
    }
}

extern "C" void kernel_launch(void* const* d_in, const int* in_sizes, int n_in,
                              void* d_out, int out_size) {
    const float* x     = (const float*)d_in[0];
    const float* Wih1  = (const float*)d_in[1];
    const float* Whh1  = (const float*)d_in[2];
    const float* bih1  = (const float*)d_in[3];
    const float* bhh1  = (const float*)d_in[4];
    const float* Wih2  = (const float*)d_in[5];
    const float* Whh2  = (const float*)d_in[6];
    const float* bih2  = (const float*)d_in[7];
    const float* bhh2  = (const float*)d_in[8];
    const float* Wlin  = (const float*)d_in[9];
    const float* blin  = (const float*)d_in[10];
    float* out = (float*)d_out;

    (void)in_sizes; (void)n_in; (void)out_size;

    static_assert(sizeof(Smem) <= 232448, "smem over sm_103a opt-in limit");
    cudaFuncSetAttribute(lstm_persistent_kernel,
                         cudaFuncAttributeMaxDynamicSharedMemorySize,
                         (int)sizeof(Smem));
    lstm_persistent_kernel<<<NCTA, NTHR, sizeof(Smem)>>>(
        x, Wih1, Whh1, bih1, bhh1, Wih2, Whh2, bih2, bhh2, Wlin, blin, out);
}

// round 11
// speedup vs baseline: 1.0954x; 1.0954x over previous
#include <cuda_runtime.h>
#include <cuda_bf16.h>

#define BATCH 1024
#define SEQ   512
#define HID   64
#define GATES 256
#define NR    8
#define NCTA  (BATCH / NR)   // 128
#define NTHR  384            // 12 warps: 8 L2-warps (4 k-groups x 2 halves) + 4 L1-warps

typedef unsigned long long ull;

struct __align__(16) Smem {
    // Weight layout: W[k][col], col = j*4 + hq (cell j, gate hq: 0=i,1=f,2=g,3=o)
    float W1[HID][GATES];          //  64 KB (W_hh1)
    float W2[2 * HID][GATES];      // 128 KB ([W_ih2 ; W_hh2])
    float hb1[2][HID][NR];         //   4 KB h1, double-buffered [t&1][k][row]
    float hb2[HID][NR];            //   2 KB h2 (single buffer)
    ulonglong2 pexA[4][3][64];     //  12 KB [pair][slot][cell] gates (i,f) — L2 only
    ulonglong2 pexB[4][3][64];     //  12 KB gates (g,o)
    float wih1v[GATES];
    float b1v[GATES];
    float b2v[GATES];
    float wlin[HID];
    float xs[2][NR];
    float outp[4][2][2];           // [pair][hh][row-in-pair]
    float blin;
};   // ~225.5 KB

#define BAR_L2() asm volatile("bar.sync 1, 256;" ::: "memory")
#define BAR_L1() asm volatile("bar.sync 2, 128;" ::: "memory")

__device__ __forceinline__ ull pk2(float lo, float hi) {
    ull r; asm("mov.b64 %0, {%1, %2};" : "=l"(r) : "f"(lo), "f"(hi)); return r;
}
__device__ __forceinline__ void unpk(ull v, float& lo, float& hi) {
    asm("mov.b64 {%0, %1}, %2;" : "=f"(lo), "=f"(hi) : "l"(v));
}
__device__ __forceinline__ void fma2(ull& d, ull a, ull b) {
    asm("fma.rn.f32x2 %0, %1, %2, %0;" : "+l"(d) : "l"(a), "l"(b));
}
__device__ __forceinline__ ull add2(ull a, ull b) {
    ull d; asm("add.rn.f32x2 %0, %1, %2;" : "=l"(d) : "l"(a), "l"(b)); return d;
}

// MUFU.TANH (sm_75+), rel err ~2e-5
__device__ __forceinline__ float tanh_fast(float x) {
    float r; asm("tanh.approx.f32 %0, %1;" : "=f"(r) : "f"(x)); return r;
}
__device__ __forceinline__ float sigf(float v) {
    return fmaf(0.5f, tanh_fast(0.5f * v), 0.5f);
}

// 8 k-steps: acc[q][p] += h[k][rows 2p,2p+1] * w[k][cell*4+q]
__device__ __forceinline__ void gemm8(const float* __restrict__ wp,
                                      const float* __restrict__ hp,
                                      ull acc[4][4]) {
#pragma unroll
    for (int kk = 0; kk < 8; kk++) {
        float4 wv = *reinterpret_cast<const float4*>(wp + kk * GATES);
        ulonglong2 hA = *reinterpret_cast<const ulonglong2*>(hp + kk * 8);
        ulonglong2 hB = *reinterpret_cast<const ulonglong2*>(hp + kk * 8 + 4);
        ull w;
        w = pk2(wv.x, wv.x);
        fma2(acc[0][0], hA.x, w); fma2(acc[0][1], hA.y, w);
        fma2(acc[0][2], hB.x, w); fma2(acc[0][3], hB.y, w);
        w = pk2(wv.y, wv.y);
        fma2(acc[1][0], hA.x, w); fma2(acc[1][1], hA.y, w);
        fma2(acc[1][2], hB.x, w); fma2(acc[1][3], hB.y, w);
        w = pk2(wv.z, wv.z);
        fma2(acc[2][0], hA.x, w); fma2(acc[2][1], hA.y, w);
        fma2(acc[2][2], hB.x, w); fma2(acc[2][3], hB.y, w);
        w = pk2(wv.w, wv.w);
        fma2(acc[3][0], hA.x, w); fma2(acc[3][1], hA.y, w);
        fma2(acc[3][2], hB.x, w); fma2(acc[3][3], hB.y, w);
    }
}

// LSTM cell for a packed row-pair: gates (i,f,g,o) each f32x2 -> h f32x2.
__device__ __forceinline__ ull act2(ull ai, ull af, ull ag, ull ao,
                                    float& ca, float& cb) {
    float i0, i1, f0, f1, g0, g1, o0, o1;
    unpk(ai, i0, i1); unpk(af, f0, f1);
    unpk(ag, g0, g1); unpk(ao, o0, o1);
    float cA = sigf(f0) * ca + sigf(i0) * tanh_fast(g0);
    float cB = sigf(f1) * cb + sigf(i1) * tanh_fast(g1);
    ca = cA; cb = cB;
    return pk2(sigf(o0) * tanh_fast(cA), sigf(o1) * tanh_fast(cB));
}

// Extract this group's row-pair with static indices (avoid local-mem demotion).
__device__ __forceinline__ void own_pair(const ull acc[4][4], int g,
                                         ull& ai, ull& af, ull& ag, ull& ao) {
    ai = 0; af = 0; ag = 0; ao = 0;
#pragma unroll
    for (int p = 0; p < 4; p++)
        if (p == g) { ai = acc[0][p]; af = acc[1][p]; ag = acc[2][p]; ao = acc[3][p]; }
}

__global__ void __launch_bounds__(NTHR, 1)
lstm_persistent_kernel(const float* __restrict__ x,
                       const float* __restrict__ Wih1, const float* __restrict__ Whh1,
                       const float* __restrict__ bih1, const float* __restrict__ bhh1,
                       const float* __restrict__ Wih2, const float* __restrict__ Whh2,
                       const float* __restrict__ bih2, const float* __restrict__ bhh2,
                       const float* __restrict__ Wlin, const float* __restrict__ blin,
                       float* __restrict__ out) {
    extern __shared__ char smem_raw[];
    Smem& sm = *reinterpret_cast<Smem*>(smem_raw);

    const int tid  = threadIdx.x;
    const int wid  = tid >> 5;
    const int lane = tid & 31;
    const int row0 = blockIdx.x * NR;

    // ---- one-time staging ----
    for (int i = tid; i < GATES * HID; i += NTHR) {
        int gsrc = i >> 6, k = i & 63;
        int col = (gsrc & 63) * 4 + (gsrc >> 6);
        sm.W1[k][col]      = Whh1[i];
        sm.W2[k][col]      = Wih2[i];
        sm.W2[64 + k][col] = Whh2[i];
    }
    for (int gsrc = tid; gsrc < GATES; gsrc += NTHR) {
        int col = (gsrc & 63) * 4 + (gsrc >> 6);
        sm.wih1v[col] = Wih1[gsrc];
        sm.b1v[col]   = bih1[gsrc] + bhh1[gsrc];
        sm.b2v[col]   = bih2[gsrc] + bhh2[gsrc];
    }
    if (tid < HID) sm.wlin[tid] = Wlin[tid];
    if (tid == 0)  sm.blin = blin[0];
    for (int i = tid; i < 2 * HID * NR; i += NTHR)
        reinterpret_cast<float*>(sm.hb1)[i] = 0.0f;
    for (int i = tid; i < HID * NR; i += NTHR)
        reinterpret_cast<float*>(sm.hb2)[i] = 0.0f;
    if (tid < NR) {
        sm.xs[1][tid] = x[(row0 + tid) * SEQ + 0];  // x(0) for prologue
        sm.xs[0][tid] = x[(row0 + tid) * SEQ + 1];  // x(1) for GEMM(0)
    }
    __syncthreads();

    const bool isL1 = (wid >= 8);
    const int g    = wid >> 1;                       // L2 group 0..3
    const int hh   = wid & 1;
    const int kh   = lane >> 4;                      // L1 k-half
    const int j    = isL1 ? ((wid - 8) * 16 + (lane & 15)) : (hh * 32 + lane);
    const int c4   = j * 4;

    // c-state: L2 threads hold c2 for pair g; L1 threads hold c1 for pairs (2kh,2kh+1)
    float cs[4] = {0.f, 0.f, 0.f, 0.f};
    const float wl = sm.wlin[j];

    // ---- prologue: gates1(0) = b1 + x(0)*wih1 (h1(-1)=0), L1 warps -> hb1[0] ----
    if (isL1) {
        float4 wiv = *reinterpret_cast<const float4*>(&sm.wih1v[c4]);
        float4 bv  = *reinterpret_cast<const float4*>(&sm.b1v[c4]);
        ulonglong2 xq = *reinterpret_cast<const ulonglong2*>(&sm.xs[1][4 * kh]);
        ull gp0[4], gp1[4];
        float wivf[4] = {wiv.x, wiv.y, wiv.z, wiv.w};
        float bvf[4]  = {bv.x, bv.y, bv.z, bv.w};
#pragma unroll
        for (int q = 0; q < 4; q++) {
            ull b = pk2(bvf[q], bvf[q]);
            ull w = pk2(wivf[q], wivf[q]);
            gp0[q] = b; fma2(gp0[q], xq.x, w);
            gp1[q] = b; fma2(gp1[q], xq.y, w);
        }
        ull h0p = act2(gp0[0], gp0[1], gp0[2], gp0[3], cs[0], cs[1]);
        ull h1p = act2(gp1[0], gp1[1], gp1[2], gp1[3], cs[2], cs[3]);
        *reinterpret_cast<ulonglong2*>(&sm.hb1[0][j][4 * kh]) = make_ulonglong2(h0p, h1p);
    }
    __syncthreads();

    for (int t = 0; t < SEQ; t++) {
        const int cur = t & 1, nxt = cur ^ 1;

        // finalize out[t-1]
        if (t > 0 && tid < NR) {
            out[(row0 + tid) * SEQ + (t - 1)] =
                sm.blin + sm.outp[tid >> 1][0][tid & 1] + sm.outp[tid >> 1][1][tid & 1];
        }

        // ===== GEMM phase (6 balanced groups of 512 FFMA2) =====
        ull acc[4][4];
        {
            if (!isL1 && g == 0) {
                float4 bv = *reinterpret_cast<const float4*>(&sm.b2v[c4]);
                ull b;
                b = pk2(bv.x, bv.x); acc[0][0]=b; acc[0][1]=b; acc[0][2]=b; acc[0][3]=b;
                b = pk2(bv.y, bv.y); acc[1][0]=b; acc[1][1]=b; acc[1][2]=b; acc[1][3]=b;
                b = pk2(bv.z, bv.z); acc[2][0]=b; acc[2][1]=b; acc[2][2]=b; acc[2][3]=b;
                b = pk2(bv.w, bv.w); acc[3][0]=b; acc[3][1]=b; acc[3][2]=b; acc[3][3]=b;
            } else if (isL1 && kh == 0) {
                float4 wiv = *reinterpret_cast<const float4*>(&sm.wih1v[c4]);
                float4 bv  = *reinterpret_cast<const float4*>(&sm.b1v[c4]);
                const float* xp = sm.xs[cur];     // x(t+1)
                ulonglong2 xA = *reinterpret_cast<const ulonglong2*>(xp);
                ulonglong2 xB = *reinterpret_cast<const ulonglong2*>(xp + 4);
                float wivf[4] = {wiv.x, wiv.y, wiv.z, wiv.w};
                float bvf[4]  = {bv.x, bv.y, bv.z, bv.w};
#pragma unroll
                for (int q = 0; q < 4; q++) {
                    ull b = pk2(bvf[q], bvf[q]);
                    ull w = pk2(wivf[q], wivf[q]);
                    acc[q][0] = b; fma2(acc[q][0], xA.x, w);
                    acc[q][1] = b; fma2(acc[q][1], xA.y, w);
                    acc[q][2] = b; fma2(acc[q][2], xB.x, w);
                    acc[q][3] = b; fma2(acc[q][3], xB.y, w);
                }
            } else {
#pragma unroll
                for (int q = 0; q < 4; q++)
#pragma unroll
                    for (int p = 0; p < 4; p++) acc[q][p] = 0ull;
            }
            const float* wp;
            const float* hp;
            if (!isL1) {   // gates2(t): k slice g*32 of [h1(t); h2(t-1)]
                wp = &sm.W2[g * 32][c4];
                hp = (g < 2) ? &sm.hb1[cur][g * 32][0] : &sm.hb2[(g - 2) * 32][0];
            } else {       // gates1(t+1): k slice kh*32 of h1(t)
                wp = &sm.W1[kh * 32][c4];
                hp = &sm.hb1[cur][kh * 32][0];
            }
#pragma unroll 1
            for (int kb = 0; kb < 4; kb++) {
                gemm8(wp, hp, acc);
                wp += 8 * GATES; hp += 8 * NR;
            }
        }

        // ===== family-local barrier + ACT =====
        if (!isL1) {
            // ship partials for pairs we don't own
#pragma unroll
            for (int p = 0; p < 4; p++)
                if (p != g) {
                    int s = (g < p) ? g : g - 1;
                    sm.pexA[p][s][j] = make_ulonglong2(acc[0][p], acc[1][p]);
                    sm.pexB[p][s][j] = make_ulonglong2(acc[2][p], acc[3][p]);
                }
            BAR_L2();   // orders: all L2 GEMM reads of h2 + pex writes
            ull ai, af, ag, ao;
            own_pair(acc, g, ai, af, ag, ao);
#pragma unroll
            for (int s = 0; s < 3; s++) {
                ulonglong2 ra = sm.pexA[g][s][j];
                ulonglong2 rb = sm.pexB[g][s][j];
                ai = add2(ai, ra.x); af = add2(af, ra.y);
                ag = add2(ag, rb.x); ao = add2(ao, rb.y);
            }
            ull h2p = act2(ai, af, ag, ao, cs[0], cs[1]);
            *reinterpret_cast<ull*>(&sm.hb2[j][2 * g]) = h2p;

            float h0, h1;
            unpk(h2p, h0, h1);
            float p0 = wl * h0, p1 = wl * h1;
#pragma unroll
            for (int off = 16; off > 0; off >>= 1) {
                p0 += __shfl_xor_sync(0xffffffffu, p0, off);
                p1 += __shfl_xor_sync(0xffffffffu, p1, off);
            }
            if (lane == 0) {
                sm.outp[g][hh][0] = p0;
                sm.outp[g][hh][1] = p1;
            }
        } else {
            BAR_L1();   // orders: all L1 GEMM reads of h1(t) vs... (write goes to nxt buf;
                        // barrier needed so next step's reads see all 4 warps' writes
                        // before the FULL barrier? The full barrier covers that; this one
                        // is kept so warps 8-11 don't race hb1[nxt] writes vs own reads.)
            ull gp0[4], gp1[4];
#pragma unroll
            for (int q = 0; q < 4; q++) {
                ull s0 = kh ? acc[q][0] : acc[q][2];
                ull s1 = kh ? acc[q][1] : acc[q][3];
                ull r0 = __shfl_xor_sync(0xffffffffu, s0, 16);
                ull r1 = __shfl_xor_sync(0xffffffffu, s1, 16);
                ull o0 = kh ? acc[q][2] : acc[q][0];
                ull o1 = kh ? acc[q][3] : acc[q][1];
                gp0[q] = add2(o0, r0);
                gp1[q] = add2(o1, r1);
            }
            ull h0p = act2(gp0[0], gp0[1], gp0[2], gp0[3], cs[0], cs[1]);
            ull h1p = act2(gp1[0], gp1[1], gp1[2], gp1[3], cs[2], cs[3]);
            *reinterpret_cast<ulonglong2*>(&sm.hb1[nxt][j][4 * kh]) =
                make_ulonglong2(h0p, h1p);
        }
        // prefetch x(t+2)
        if (tid < NR && (t + 2) < SEQ)
            sm.xs[nxt][tid] = x[(row0 + tid) * SEQ + t + 2];
        __syncthreads();   // cross-family hand-off: h1(t+1), h2(t), outp, xs
    }

    if (tid < NR) {
        out[(row0 + tid) * SEQ + (SEQ - 1)] =
            sm.blin + sm.outp[tid >> 1][0][tid & 1] + sm.outp[tid >> 1][1][tid & 1];
    }
}

extern "C" void kernel_launch(void* const* d_in, const int* in_sizes, int n_in,
                              void* d_out, int out_size) {
    const float* x     = (const float*)d_in[0];
    const float* Wih1  = (const float*)d_in[1];
    const float* Whh1  = (const float*)d_in[2];
    const float* bih1  = (const float*)d_in[3];
    const float* bhh1  = (const float*)d_in[4];
    const float* Wih2  = (const float*)d_in[5];
    const float* Whh2  = (const float*)d_in[6];
    const float* bih2  = (const float*)d_in[7];
    const float* bhh2  = (const float*)d_in[8];
    const float* Wlin  = (const float*)d_in[9];
    const float* blin  = (const float*)d_in[10];
    float* out = (float*)d_out;

    (void)in_sizes; (void)n_in; (void)out_size;

    static_assert(sizeof(Smem) <= 232448, "smem over sm_103a opt-in limit");
    cudaFuncSetAttribute(lstm_persistent_kernel,
                         cudaFuncAttributeMaxDynamicSharedMemorySize,
                         (int)sizeof(Smem));
    lstm_persistent_kernel<<<NCTA, NTHR, sizeof(Smem)>>>(
        x, Wih1, Whh1, bih1, bhh1, Wih2, Whh2, bih2, bhh2, Wlin, blin, out);
}

// round 13
// speedup vs baseline: 1.2465x; 1.1379x over previous
#include <cuda_runtime.h>
#include <cuda_bf16.h>

#define BATCH 1024
#define SEQ   512
#define HID   64
#define GATES 256
#define NR    8
#define NCTA  (BATCH / NR)   // 128
#define NTHR  384            // 12 warps: 8 L2 (gates2) + 4 L1 (gates1 next)

typedef unsigned long long ull;

struct __align__(16) Smem {
    // Weight layout: W[k][col], col = j*4 + hq (cell j, gate hq: 0=i,1=f,2=g,3=o)
    float W1[HID][GATES];          //  64 KB (W_hh1)
    float W2[2 * HID][GATES];      // 128 KB ([W_ih2 ; W_hh2])
    float hb1[2][HID][NR];         //   4 KB h1 double-buffered [buf][k][row]
    float hb2[2][HID][NR];         //   4 KB h2 double-buffered
    float wih1v[GATES];
    float b1v[GATES];
    float b2v[GATES];
    float wlin[HID];
    float xs[2][NR];
    float outp[2][4][2][8];        // [buf][pair][row-in-pair][l2-warp]
    float blin;
};   // ~204 KB

__device__ __forceinline__ ull pk2(float lo, float hi) {
    ull r; asm("mov.b64 %0, {%1, %2};" : "=l"(r) : "f"(lo), "f"(hi)); return r;
}
__device__ __forceinline__ void unpk(ull v, float& lo, float& hi) {
    asm("mov.b64 {%0, %1}, %2;" : "=f"(lo), "=f"(hi) : "l"(v));
}
__device__ __forceinline__ void fma2(ull& d, ull a, ull b) {
    asm("fma.rn.f32x2 %0, %1, %2, %0;" : "+l"(d) : "l"(a), "l"(b));
}
__device__ __forceinline__ ull add2(ull a, ull b) {
    ull d; asm("add.rn.f32x2 %0, %1, %2;" : "=l"(d) : "l"(a), "l"(b)); return d;
}

// MUFU.TANH (sm_75+), rel err ~2e-5
__device__ __forceinline__ float tanh_fast(float x) {
    float r; asm("tanh.approx.f32 %0, %1;" : "=f"(r) : "f"(x)); return r;
}
__device__ __forceinline__ float sigf(float v) {
    return fmaf(0.5f, tanh_fast(0.5f * v), 0.5f);
}

// 8 strided k-steps: acc[q][p] += h[m][rows 2p,2p+1] * w[m][q], strides WS/HS floats
template <int WS, int HS>
__device__ __forceinline__ void gemm8s(const float* __restrict__ wp,
                                       const float* __restrict__ hp,
                                       ull acc[4][4]) {
#pragma unroll
    for (int m = 0; m < 8; m++) {
        float4 wv = *reinterpret_cast<const float4*>(wp + m * WS);
        ulonglong2 hA = *reinterpret_cast<const ulonglong2*>(hp + m * HS);
        ulonglong2 hB = *reinterpret_cast<const ulonglong2*>(hp + m * HS + 4);
        ull w;
        w = pk2(wv.x, wv.x);
        fma2(acc[0][0], hA.x, w); fma2(acc[0][1], hA.y, w);
        fma2(acc[0][2], hB.x, w); fma2(acc[0][3], hB.y, w);
        w = pk2(wv.y, wv.y);
        fma2(acc[1][0], hA.x, w); fma2(acc[1][1], hA.y, w);
        fma2(acc[1][2], hB.x, w); fma2(acc[1][3], hB.y, w);
        w = pk2(wv.z, wv.z);
        fma2(acc[2][0], hA.x, w); fma2(acc[2][1], hA.y, w);
        fma2(acc[2][2], hB.x, w); fma2(acc[2][3], hB.y, w);
        w = pk2(wv.w, wv.w);
        fma2(acc[3][0], hA.x, w); fma2(acc[3][1], hA.y, w);
        fma2(acc[3][2], hB.x, w); fma2(acc[3][3], hB.y, w);
    }
}

// LSTM cell for a packed row-pair.
__device__ __forceinline__ ull act2(ull ai, ull af, ull ag, ull ao,
                                    float& ca, float& cb) {
    float i0, i1, f0, f1, g0, g1, o0, o1;
    unpk(ai, i0, i1); unpk(af, f0, f1);
    unpk(ag, g0, g1); unpk(ao, o0, o1);
    float cA = sigf(f0) * ca + sigf(i0) * tanh_fast(g0);
    float cB = sigf(f1) * cb + sigf(i1) * tanh_fast(g1);
    ca = cA; cb = cB;
    return pk2(sigf(o0) * tanh_fast(cA), sigf(o1) * tanh_fast(cB));
}

__global__ void __launch_bounds__(NTHR, 1)
lstm_persistent_kernel(const float* __restrict__ x,
                       const float* __restrict__ Wih1, const float* __restrict__ Whh1,
                       const float* __restrict__ bih1, const float* __restrict__ bhh1,
                       const float* __restrict__ Wih2, const float* __restrict__ Whh2,
                       const float* __restrict__ bih2, const float* __restrict__ bhh2,
                       const float* __restrict__ Wlin, const float* __restrict__ blin,
                       float* __restrict__ out) {
    extern __shared__ char smem_raw[];
    Smem& sm = *reinterpret_cast<Smem*>(smem_raw);

    const int tid  = threadIdx.x;
    const int wid  = tid >> 5;
    const int lane = tid & 31;
    const int row0 = blockIdx.x * NR;

    // ---- one-time staging ----
    for (int i = tid; i < GATES * HID; i += NTHR) {
        int gsrc = i >> 6, k = i & 63;
        int col = (gsrc & 63) * 4 + (gsrc >> 6);
        sm.W1[k][col]      = Whh1[i];
        sm.W2[k][col]      = Wih2[i];
        sm.W2[64 + k][col] = Whh2[i];
    }
    for (int gsrc = tid; gsrc < GATES; gsrc += NTHR) {
        int col = (gsrc & 63) * 4 + (gsrc >> 6);
        sm.wih1v[col] = Wih1[gsrc];
        sm.b1v[col]   = bih1[gsrc] + bhh1[gsrc];
        sm.b2v[col]   = bih2[gsrc] + bhh2[gsrc];
    }
    if (tid < HID) sm.wlin[tid] = Wlin[tid];
    if (tid == 0)  sm.blin = blin[0];
    // zero state buffers (each is 2*HID*NR = 1024 floats — bound fixed vs R12)
    for (int i = tid; i < 2 * HID * NR; i += NTHR) {
        reinterpret_cast<float*>(sm.hb1)[i] = 0.0f;
        reinterpret_cast<float*>(sm.hb2)[i] = 0.0f;
    }
    if (tid < NR) {
        sm.xs[1][tid] = x[(row0 + tid) * SEQ + 0];  // x(0) for prologue
        sm.xs[0][tid] = x[(row0 + tid) * SEQ + 1];  // x(1) for GEMM(0)
    }
    __syncthreads();

    const bool isL1 = (wid >= 8);
    // L2: warp owns 8 cells; lane = kq*8 + cell-in-warp; k-interleave kq+4m
    // L1: warp owns 16 cells; lane = kh*16 + cell-in-warp; k-interleave kh+2m
    const int kq   = lane >> 3;                      // L2 k-quarter / owned pair
    const int kh   = lane >> 4;                      // L1 k-half
    const int j    = isL1 ? ((wid - 8) * 16 + (lane & 15)) : (wid * 8 + (lane & 7));
    const int c4   = j * 4;

    // c-state: L2 lane holds c2 for pair kq (2 rows); L1 lane c1 for pairs 2kh,2kh+1
    float cs[4] = {0.f, 0.f, 0.f, 0.f};
    const float wl = sm.wlin[j];

    // ---- prologue: h1(0) = act(b1 + x(0)*wih1), L1 warps -> hb1[0] ----
    if (isL1) {
        float4 wiv = *reinterpret_cast<const float4*>(&sm.wih1v[c4]);
        float4 bv  = *reinterpret_cast<const float4*>(&sm.b1v[c4]);
        ulonglong2 xq = *reinterpret_cast<const ulonglong2*>(&sm.xs[1][4 * kh]);
        float wivf[4] = {wiv.x, wiv.y, wiv.z, wiv.w};
        float bvf[4]  = {bv.x, bv.y, bv.z, bv.w};
        ull gp0[4], gp1[4];
#pragma unroll
        for (int q = 0; q < 4; q++) {
            ull b = pk2(bvf[q], bvf[q]);
            ull w = pk2(wivf[q], wivf[q]);
            gp0[q] = b; fma2(gp0[q], xq.x, w);
            gp1[q] = b; fma2(gp1[q], xq.y, w);
        }
        ull h0p = act2(gp0[0], gp0[1], gp0[2], gp0[3], cs[0], cs[1]);
        ull h1p = act2(gp1[0], gp1[1], gp1[2], gp1[3], cs[2], cs[3]);
        *reinterpret_cast<ulonglong2*>(&sm.hb1[0][j][4 * kh]) = make_ulonglong2(h0p, h1p);
    }
    __syncthreads();

    for (int t = 0; t < SEQ; t++) {
        const int cur = t & 1, nxt = cur ^ 1;

        // finalize out[t-1] from outp[cur] (written during step t-1)
        if (t > 0 && tid < NR) {
            const float* op = &sm.outp[cur][tid >> 1][tid & 1][0];
            float4 a = *reinterpret_cast<const float4*>(op);
            float4 b = *reinterpret_cast<const float4*>(op + 4);
            out[(row0 + tid) * SEQ + (t - 1)] =
                sm.blin + ((a.x + a.y) + (a.z + a.w)) + ((b.x + b.y) + (b.z + b.w));
        }

        // ===== GEMM phase (pure accumulate, bias added post-reduce) =====
        ull acc[4][4];
#pragma unroll
        for (int q = 0; q < 4; q++)
#pragma unroll
            for (int p = 0; p < 4; p++) acc[q][p] = 0ull;

        if (!isL1) {
            // gates2(t): lane k = kq+4m; m<16 -> h1(t), m>=16 -> h2(t-1)
            const float* wp  = &sm.W2[kq][c4];
            const float* h1p = &sm.hb1[cur][kq][0];
            const float* h2p = &sm.hb2[cur][kq][0];
            gemm8s<4 * GATES, 4 * NR>(wp,                  h1p,              acc);
            gemm8s<4 * GATES, 4 * NR>(wp +  8 * 4 * GATES, h1p + 8 * 4 * NR, acc);
            gemm8s<4 * GATES, 4 * NR>(wp + 16 * 4 * GATES, h2p,              acc);
            gemm8s<4 * GATES, 4 * NR>(wp + 24 * 4 * GATES, h2p + 8 * 4 * NR, acc);
        } else {
            // gates1(t+1): lane k = kh+2m over h1(t)
            const float* wp = &sm.W1[kh][c4];
            const float* hp = &sm.hb1[cur][kh][0];
            gemm8s<2 * GATES, 2 * NR>(wp,                  hp,               acc);
            gemm8s<2 * GATES, 2 * NR>(wp +  8 * 2 * GATES, hp +  8 * 2 * NR, acc);
            gemm8s<2 * GATES, 2 * NR>(wp + 16 * 2 * GATES, hp + 16 * 2 * NR, acc);
            gemm8s<2 * GATES, 2 * NR>(wp + 24 * 2 * GATES, hp + 24 * 2 * NR, acc);
        }

        // ===== intra-warp k-reduce + ACT (no SMEM exchange, no mid barrier) =====
        if (!isL1) {
            // 4-way butterfly: xor-16 (kq^2), xor-8 (kq^1); lane ends with pair kq
            const bool lowkq = (kq < 2);
            ull a0[4], a1[4];
#pragma unroll
            for (int q = 0; q < 4; q++) {
                ull s0 = lowkq ? acc[q][2] : acc[q][0];
                ull s1 = lowkq ? acc[q][3] : acc[q][1];
                ull r0 = __shfl_xor_sync(0xffffffffu, s0, 16);
                ull r1 = __shfl_xor_sync(0xffffffffu, s1, 16);
                ull k0 = lowkq ? acc[q][0] : acc[q][2];
                ull k1 = lowkq ? acc[q][1] : acc[q][3];
                a0[q] = add2(k0, r0);
                a1[q] = add2(k1, r1);
            }
            const bool evenkq = ((kq & 1) == 0);
            float4 bv = *reinterpret_cast<const float4*>(&sm.b2v[c4]);
            float bvf[4] = {bv.x, bv.y, bv.z, bv.w};
            ull g[4];
#pragma unroll
            for (int q = 0; q < 4; q++) {
                ull s = evenkq ? a1[q] : a0[q];
                ull r = __shfl_xor_sync(0xffffffffu, s, 8);
                ull k = evenkq ? a0[q] : a1[q];
                g[q] = add2(add2(k, r), pk2(bvf[q], bvf[q]));
            }
            ull h2p = act2(g[0], g[1], g[2], g[3], cs[0], cs[1]);
            *reinterpret_cast<ull*>(&sm.hb2[nxt][j][2 * kq]) = h2p;

            // out partials: octet-reduce over this warp's 8 cells (lanes same kq)
            float h0, h1;
            unpk(h2p, h0, h1);
            float p0 = wl * h0, p1 = wl * h1;
#pragma unroll
            for (int off = 1; off < 8; off <<= 1) {
                p0 += __shfl_xor_sync(0xffffffffu, p0, off);
                p1 += __shfl_xor_sync(0xffffffffu, p1, off);
            }
            if ((lane & 7) == 0) {
                sm.outp[nxt][kq][0][wid] = p0;
                sm.outp[nxt][kq][1][wid] = p1;
            }
        } else {
            // 2-way reduce via xor-16; lane ends with pairs 2kh, 2kh+1
            ull gp0[4], gp1[4];
#pragma unroll
            for (int q = 0; q < 4; q++) {
                ull s0 = kh ? acc[q][0] : acc[q][2];
                ull s1 = kh ? acc[q][1] : acc[q][3];
                ull r0 = __shfl_xor_sync(0xffffffffu, s0, 16);
                ull r1 = __shfl_xor_sync(0xffffffffu, s1, 16);
                ull o0 = kh ? acc[q][2] : acc[q][0];
                ull o1 = kh ? acc[q][3] : acc[q][1];
                gp0[q] = add2(o0, r0);
                gp1[q] = add2(o1, r1);
            }
            // add bias + x(t+1) term post-reduce
            float4 wiv = *reinterpret_cast<const float4*>(&sm.wih1v[c4]);
            float4 bv  = *reinterpret_cast<const float4*>(&sm.b1v[c4]);
            ulonglong2 xq = *reinterpret_cast<const ulonglong2*>(&sm.xs[cur][4 * kh]);
            float wivf[4] = {wiv.x, wiv.y, wiv.z, wiv.w};
            float bvf[4]  = {bv.x, bv.y, bv.z, bv.w};
#pragma unroll
            for (int q = 0; q < 4; q++) {
                ull w = pk2(wivf[q], wivf[q]);
                ull t0 = pk2(bvf[q], bvf[q]); fma2(t0, xq.x, w);
                ull t1 = pk2(bvf[q], bvf[q]); fma2(t1, xq.y, w);
                gp0[q] = add2(gp0[q], t0);
                gp1[q] = add2(gp1[q], t1);
            }
            ull h0p = act2(gp0[0], gp0[1], gp0[2], gp0[3], cs[0], cs[1]);
            ull h1p = act2(gp1[0], gp1[1], gp1[2], gp1[3], cs[2], cs[3]);
            *reinterpret_cast<ulonglong2*>(&sm.hb1[nxt][j][4 * kh]) =
                make_ulonglong2(h0p, h1p);
        }
        // prefetch x(t+2) into xs[nxt]
        if (tid < NR && (t + 2) < SEQ)
            sm.xs[nxt][tid] = x[(row0 + tid) * SEQ + t + 2];

        __syncthreads();   // single per-step hand-off
    }

    // finalize out[SEQ-1] from outp[SEQ & 1]
    if (tid < NR) {
        const float* op = &sm.outp[SEQ & 1][tid >> 1][tid & 1][0];
        float4 a = *reinterpret_cast<const float4*>(op);
        float4 b = *reinterpret_cast<const float4*>(op + 4);
        out[(row0 + tid) * SEQ + (SEQ - 1)] =
            sm.blin + ((a.x + a.y) + (a.z + a.w)) + ((b.x + b.y) + (b.z + b.w));
    }
}

extern "C" void kernel_launch(void* const* d_in, const int* in_sizes, int n_in,
                              void* d_out, int out_size) {
    const float* x     = (const float*)d_in[0];
    const float* Wih1  = (const float*)d_in[1];
    const float* Whh1  = (const float*)d_in[2];
    const float* bih1  = (const float*)d_in[3];
    const float* bhh1  = (const float*)d_in[4];
    const float* Wih2  = (const float*)d_in[5];
    const float* Whh2  = (const float*)d_in[6];
    const float* bih2  = (const float*)d_in[7];
    const float* bhh2  = (const float*)d_in[8];
    const float* Wlin  = (const float*)d_in[9];
    const float* blin  = (const float*)d_in[10];
    float* out = (float*)d_out;

    (void)in_sizes; (void)n_in; (void)out_size;

    static_assert(sizeof(Smem) <= 232448, "smem over sm_103a opt-in limit");
    cudaFuncSetAttribute(lstm_persistent_kernel,
                         cudaFuncAttributeMaxDynamicSharedMemorySize,
                         (int)sizeof(Smem));
    lstm_persistent_kernel<<<NCTA, NTHR, sizeof(Smem)>>>(
        x, Wih1, Whh1, bih1, bhh1, Wih2, Whh2, bih2, bhh2, Wlin, blin, out);
}

// round 14
// speedup vs baseline: 1.2686x; 1.0177x over previous
#include <cuda_runtime.h>
#include <cuda_bf16.h>

#define BATCH 1024
#define SEQ   512
#define HID   64
#define GATES 256
#define NR    8
#define NCTA  (BATCH / NR)   // 128
#define NTHR  384            // 12 warps: 8 L2 (gates2) + 4 L1 (gates1 next)

typedef unsigned long long ull;

struct __align__(16) Smem {
    // Weight layout: W[k][col], col = j*4 + hq (cell j, gate hq: 0=i,1=f,2=g,3=o)
    float W1[HID][GATES];          //  64 KB (W_hh1)
    float W2[2 * HID][GATES];      // 128 KB ([W_ih2 ; W_hh2])
    float hb1[2][HID][NR];         //   4 KB h1 double-buffered [buf][k][row]
    float hb2[2][HID][NR];         //   4 KB h2 double-buffered
    float wih1v[GATES];
    float b1v[GATES];
    float b2v[GATES];
    float wlin[HID];
    float xs[2][NR];
    float outp[2][4][2][8];        // [buf][pair][row-in-pair][l2-warp]
    float blin;
};   // ~204 KB

__device__ __forceinline__ ull pk2(float lo, float hi) {
    ull r; asm("mov.b64 %0, {%1, %2};" : "=l"(r) : "f"(lo), "f"(hi)); return r;
}
__device__ __forceinline__ void unpk(ull v, float& lo, float& hi) {
    asm("mov.b64 {%0, %1}, %2;" : "=f"(lo), "=f"(hi) : "l"(v));
}
__device__ __forceinline__ void fma2(ull& d, ull a, ull b) {
    asm("fma.rn.f32x2 %0, %1, %2, %0;" : "+l"(d) : "l"(a), "l"(b));
}
__device__ __forceinline__ ull add2(ull a, ull b) {
    ull d; asm("add.rn.f32x2 %0, %1, %2;" : "=l"(d) : "l"(a), "l"(b)); return d;
}

// MUFU.TANH (sm_75+), rel err ~2e-5
__device__ __forceinline__ float tanh_fast(float x) {
    float r; asm("tanh.approx.f32 %0, %1;" : "=f"(r) : "f"(x)); return r;
}
__device__ __forceinline__ float sigf(float v) {
    return fmaf(0.5f, tanh_fast(0.5f * v), 0.5f);
}

__device__ __forceinline__ void fma16(float4 wv, ulonglong2 hA, ulonglong2 hB,
                                      ull acc[4][4]) {
    ull w;
    w = pk2(wv.x, wv.x);
    fma2(acc[0][0], hA.x, w); fma2(acc[0][1], hA.y, w);
    fma2(acc[0][2], hB.x, w); fma2(acc[0][3], hB.y, w);
    w = pk2(wv.y, wv.y);
    fma2(acc[1][0], hA.x, w); fma2(acc[1][1], hA.y, w);
    fma2(acc[1][2], hB.x, w); fma2(acc[1][3], hB.y, w);
    w = pk2(wv.z, wv.z);
    fma2(acc[2][0], hA.x, w); fma2(acc[2][1], hA.y, w);
    fma2(acc[2][2], hB.x, w); fma2(acc[2][3], hB.y, w);
    w = pk2(wv.w, wv.w);
    fma2(acc[3][0], hA.x, w); fma2(acc[3][1], hA.y, w);
    fma2(acc[3][2], hB.x, w); fma2(acc[3][3], hB.y, w);
}

// 8 strided k-steps, weights from SMEM
template <int WS, int HS>
__device__ __forceinline__ void gemm8s(const float* __restrict__ wp,
                                       const float* __restrict__ hp,
                                       ull acc[4][4]) {
#pragma unroll
    for (int m = 0; m < 8; m++) {
        float4 wv = *reinterpret_cast<const float4*>(wp + m * WS);
        ulonglong2 hA = *reinterpret_cast<const ulonglong2*>(hp + m * HS);
        ulonglong2 hB = *reinterpret_cast<const ulonglong2*>(hp + m * HS + 4);
        fma16(wv, hA, hB, acc);
    }
}

// 8 strided k-steps, weights from registers (loop-invariant cache)
template <int HS>
__device__ __forceinline__ void gemm8r(const float4 wreg[8],
                                       const float* __restrict__ hp,
                                       ull acc[4][4]) {
#pragma unroll
    for (int m = 0; m < 8; m++) {
        ulonglong2 hA = *reinterpret_cast<const ulonglong2*>(hp + m * HS);
        ulonglong2 hB = *reinterpret_cast<const ulonglong2*>(hp + m * HS + 4);
        fma16(wreg[m], hA, hB, acc);
    }
}

// LSTM cell for a packed row-pair.
__device__ __forceinline__ ull act2(ull ai, ull af, ull ag, ull ao,
                                    float& ca, float& cb) {
    float i0, i1, f0, f1, g0, g1, o0, o1;
    unpk(ai, i0, i1); unpk(af, f0, f1);
    unpk(ag, g0, g1); unpk(ao, o0, o1);
    float cA = sigf(f0) * ca + sigf(i0) * tanh_fast(g0);
    float cB = sigf(f1) * cb + sigf(i1) * tanh_fast(g1);
    ca = cA; cb = cB;
    return pk2(sigf(o0) * tanh_fast(cA), sigf(o1) * tanh_fast(cB));
}

__global__ void __launch_bounds__(NTHR, 1)
lstm_persistent_kernel(const float* __restrict__ x,
                       const float* __restrict__ Wih1, const float* __restrict__ Whh1,
                       const float* __restrict__ bih1, const float* __restrict__ bhh1,
                       const float* __restrict__ Wih2, const float* __restrict__ Whh2,
                       const float* __restrict__ bih2, const float* __restrict__ bhh2,
                       const float* __restrict__ Wlin, const float* __restrict__ blin,
                       float* __restrict__ out) {
    extern __shared__ char smem_raw[];
    Smem& sm = *reinterpret_cast<Smem*>(smem_raw);

    const int tid  = threadIdx.x;
    const int wid  = tid >> 5;
    const int lane = tid & 31;
    const int row0 = blockIdx.x * NR;

    // ---- one-time staging ----
    for (int i = tid; i < GATES * HID; i += NTHR) {
        int gsrc = i >> 6, k = i & 63;
        int col = (gsrc & 63) * 4 + (gsrc >> 6);
        sm.W1[k][col]      = Whh1[i];
        sm.W2[k][col]      = Wih2[i];
        sm.W2[64 + k][col] = Whh2[i];
    }
    for (int gsrc = tid; gsrc < GATES; gsrc += NTHR) {
        int col = (gsrc & 63) * 4 + (gsrc >> 6);
        sm.wih1v[col] = Wih1[gsrc];
        sm.b1v[col]   = bih1[gsrc] + bhh1[gsrc];
        sm.b2v[col]   = bih2[gsrc] + bhh2[gsrc];
    }
    if (tid < HID) sm.wlin[tid] = Wlin[tid];
    if (tid == 0)  sm.blin = blin[0];
    for (int i = tid; i < 2 * HID * NR; i += NTHR) {
        reinterpret_cast<float*>(sm.hb1)[i] = 0.0f;
        reinterpret_cast<float*>(sm.hb2)[i] = 0.0f;
    }
    if (tid < NR) {
        sm.xs[1][tid] = x[(row0 + tid) * SEQ + 0];  // x(0) for prologue
        sm.xs[0][tid] = x[(row0 + tid) * SEQ + 1];  // x(1) for GEMM(0)
    }
    __syncthreads();

    const bool isL1 = (wid >= 8);
    // L2: warp owns 8 cells; lane = kq*8 + cell-in-warp; k-interleave kq+4m
    // L1: warp owns 16 cells; lane = kh*16 + cell-in-warp; k-interleave kh+2m
    const int kq   = lane >> 3;                      // L2 k-quarter / owned pair
    const int kh   = lane >> 4;                      // L1 k-half
    const int j    = isL1 ? ((wid - 8) * 16 + (lane & 15)) : (wid * 8 + (lane & 7));
    const int c4   = j * 4;

    // register-resident weight cache: first 8 k-slices of this thread's strip
    float4 wreg[8];
    if (!isL1) {
        const float* wp = &sm.W2[kq][c4];
#pragma unroll
        for (int m = 0; m < 8; m++)
            wreg[m] = *reinterpret_cast<const float4*>(wp + m * 4 * GATES);
    } else {
        const float* wp = &sm.W1[kh][c4];
#pragma unroll
        for (int m = 0; m < 8; m++)
            wreg[m] = *reinterpret_cast<const float4*>(wp + m * 2 * GATES);
    }

    // c-state: L2 lane holds c2 for pair kq; L1 lane c1 for pairs 2kh, 2kh+1
    float cs[4] = {0.f, 0.f, 0.f, 0.f};
    const float wl = sm.wlin[j];

    // ---- prologue: h1(0) = act(b1 + x(0)*wih1), L1 warps -> hb1[0] ----
    if (isL1) {
        float4 wiv = *reinterpret_cast<const float4*>(&sm.wih1v[c4]);
        float4 bv  = *reinterpret_cast<const float4*>(&sm.b1v[c4]);
        ulonglong2 xq = *reinterpret_cast<const ulonglong2*>(&sm.xs[1][4 * kh]);
        float wivf[4] = {wiv.x, wiv.y, wiv.z, wiv.w};
        float bvf[4]  = {bv.x, bv.y, bv.z, bv.w};
        ull gp0[4], gp1[4];
#pragma unroll
        for (int q = 0; q < 4; q++) {
            ull b = pk2(bvf[q], bvf[q]);
            ull w = pk2(wivf[q], wivf[q]);
            gp0[q] = b; fma2(gp0[q], xq.x, w);
            gp1[q] = b; fma2(gp1[q], xq.y, w);
        }
        ull h0p = act2(gp0[0], gp0[1], gp0[2], gp0[3], cs[0], cs[1]);
        ull h1p = act2(gp1[0], gp1[1], gp1[2], gp1[3], cs[2], cs[3]);
        *reinterpret_cast<ulonglong2*>(&sm.hb1[0][j][4 * kh]) = make_ulonglong2(h0p, h1p);
    }
    __syncthreads();

    for (int t = 0; t < SEQ; t++) {
        const int cur = t & 1, nxt = cur ^ 1;

        // finalize out[t-1] from outp[cur] (written during step t-1)
        if (t > 0 && tid < NR) {
            const float* op = &sm.outp[cur][tid >> 1][tid & 1][0];
            float4 a = *reinterpret_cast<const float4*>(op);
            float4 b = *reinterpret_cast<const float4*>(op + 4);
            out[(row0 + tid) * SEQ + (t - 1)] =
                sm.blin + ((a.x + a.y) + (a.z + a.w)) + ((b.x + b.y) + (b.z + b.w));
        }

        // ===== GEMM phase (pure accumulate, bias added post-reduce) =====
        ull acc[4][4];
#pragma unroll
        for (int q = 0; q < 4; q++)
#pragma unroll
            for (int p = 0; p < 4; p++) acc[q][p] = 0ull;

        if (!isL1) {
            // gates2(t): lane k = kq+4m; m<16 -> h1(t), m>=16 -> h2(t-1)
            const float* wp  = &sm.W2[kq][c4];
            const float* h1p = &sm.hb1[cur][kq][0];
            const float* h2p = &sm.hb2[cur][kq][0];
            gemm8r<4 * NR>(wreg, h1p, acc);                                 // m 0..7 (regs)
            gemm8s<4 * GATES, 4 * NR>(wp +  8 * 4 * GATES, h1p + 8 * 4 * NR, acc);
            gemm8s<4 * GATES, 4 * NR>(wp + 16 * 4 * GATES, h2p,              acc);
            gemm8s<4 * GATES, 4 * NR>(wp + 24 * 4 * GATES, h2p + 8 * 4 * NR, acc);
        } else {
            // gates1(t+1): lane k = kh+2m over h1(t)
            const float* wp = &sm.W1[kh][c4];
            const float* hp = &sm.hb1[cur][kh][0];
            gemm8r<2 * NR>(wreg, hp, acc);                                  // m 0..7 (regs)
            gemm8s<2 * GATES, 2 * NR>(wp +  8 * 2 * GATES, hp +  8 * 2 * NR, acc);
            gemm8s<2 * GATES, 2 * NR>(wp + 16 * 2 * GATES, hp + 16 * 2 * NR, acc);
            gemm8s<2 * GATES, 2 * NR>(wp + 24 * 2 * GATES, hp + 24 * 2 * NR, acc);
        }

        // ===== intra-warp k-reduce + ACT (no SMEM exchange, no mid barrier) =====
        if (!isL1) {
            // 4-way butterfly: xor-16 (kq^2), xor-8 (kq^1); lane ends with pair kq
            const bool lowkq = (kq < 2);
            ull a0[4], a1[4];
#pragma unroll
            for (int q = 0; q < 4; q++) {
                ull s0 = lowkq ? acc[q][2] : acc[q][0];
                ull s1 = lowkq ? acc[q][3] : acc[q][1];
                ull r0 = __shfl_xor_sync(0xffffffffu, s0, 16);
                ull r1 = __shfl_xor_sync(0xffffffffu, s1, 16);
                ull k0 = lowkq ? acc[q][0] : acc[q][2];
                ull k1 = lowkq ? acc[q][1] : acc[q][3];
                a0[q] = add2(k0, r0);
                a1[q] = add2(k1, r1);
            }
            const bool evenkq = ((kq & 1) == 0);
            float4 bv = *reinterpret_cast<const float4*>(&sm.b2v[c4]);
            float bvf[4] = {bv.x, bv.y, bv.z, bv.w};
            ull g[4];
#pragma unroll
            for (int q = 0; q < 4; q++) {
                ull s = evenkq ? a1[q] : a0[q];
                ull r = __shfl_xor_sync(0xffffffffu, s, 8);
                ull k = evenkq ? a0[q] : a1[q];
                g[q] = add2(add2(k, r), pk2(bvf[q], bvf[q]));
            }
            ull h2p = act2(g[0], g[1], g[2], g[3], cs[0], cs[1]);
            *reinterpret_cast<ull*>(&sm.hb2[nxt][j][2 * kq]) = h2p;

            // out partials: octet-reduce over this warp's 8 cells (lanes same kq)
            float h0, h1;
            unpk(h2p, h0, h1);
            float p0 = wl * h0, p1 = wl * h1;
#pragma unroll
            for (int off = 1; off < 8; off <<= 1) {
                p0 += __shfl_xor_sync(0xffffffffu, p0, off);
                p1 += __shfl_xor_sync(0xffffffffu, p1, off);
            }
            if ((lane & 7) == 0) {
                sm.outp[nxt][kq][0][wid] = p0;
                sm.outp[nxt][kq][1][wid] = p1;
            }
        } else {
            // 2-way reduce via xor-16; lane ends with pairs 2kh, 2kh+1
            ull gp0[4], gp1[4];
#pragma unroll
            for (int q = 0; q < 4; q++) {
                ull s0 = kh ? acc[q][0] : acc[q][2];
                ull s1 = kh ? acc[q][1] : acc[q][3];
                ull r0 = __shfl_xor_sync(0xffffffffu, s0, 16);
                ull r1 = __shfl_xor_sync(0xffffffffu, s1, 16);
                ull o0 = kh ? acc[q][2] : acc[q][0];
                ull o1 = kh ? acc[q][3] : acc[q][1];
                gp0[q] = add2(o0, r0);
                gp1[q] = add2(o1, r1);
            }
            // add bias + x(t+1) term post-reduce
            float4 wiv = *reinterpret_cast<const float4*>(&sm.wih1v[c4]);
            float4 bv  = *reinterpret_cast<const float4*>(&sm.b1v[c4]);
            ulonglong2 xq = *reinterpret_cast<const ulonglong2*>(&sm.xs[cur][4 * kh]);
            float wivf[4] = {wiv.x, wiv.y, wiv.z, wiv.w};
            float bvf[4]  = {bv.x, bv.y, bv.z, bv.w};
#pragma unroll
            for (int q = 0; q < 4; q++) {
                ull w = pk2(wivf[q], wivf[q]);
                ull t0 = pk2(bvf[q], bvf[q]); fma2(t0, xq.x, w);
                ull t1 = pk2(bvf[q], bvf[q]); fma2(t1, xq.y, w);
                gp0[q] = add2(gp0[q], t0);
                gp1[q] = add2(gp1[q], t1);
            }
            ull h0p = act2(gp0[0], gp0[1], gp0[2], gp0[3], cs[0], cs[1]);
            ull h1p = act2(gp1[0], gp1[1], gp1[2], gp1[3], cs[2], cs[3]);
            *reinterpret_cast<ulonglong2*>(&sm.hb1[nxt][j][4 * kh]) =
                make_ulonglong2(h0p, h1p);
        }
        // prefetch x(t+2) into xs[nxt]
        if (tid < NR && (t + 2) < SEQ)
            sm.xs[nxt][tid] = x[(row0 + tid) * SEQ + t + 2];

        __syncthreads();   // single per-step hand-off
    }

    // finalize out[SEQ-1] from outp[SEQ & 1]
    if (tid < NR) {
        const float* op = &sm.outp[SEQ & 1][tid >> 1][tid & 1][0];
        float4 a = *reinterpret_cast<const float4*>(op);
        float4 b = *reinterpret_cast<const float4*>(op + 4);
        out[(row0 + tid) * SEQ + (SEQ - 1)] =
            sm.blin + ((a.x + a.y) + (a.z + a.w)) + ((b.x + b.y) + (b.z + b.w));
    }
}

extern "C" void kernel_launch(void* const* d_in, const int* in_sizes, int n_in,
                              void* d_out, int out_size) {
    const float* x     = (const float*)d_in[0];
    const float* Wih1  = (const float*)d_in[1];
    const float* Whh1  = (const float*)d_in[2];
    const float* bih1  = (const float*)d_in[3];
    const float* bhh1  = (const float*)d_in[4];
    const float* Wih2  = (const float*)d_in[5];
    const float* Whh2  = (const float*)d_in[6];
    const float* bih2  = (const float*)d_in[7];
    const float* bhh2  = (const float*)d_in[8];
    const float* Wlin  = (const float*)d_in[9];
    const float* blin  = (const float*)d_in[10];
    float* out = (float*)d_out;

    (void)in_sizes; (void)n_in; (void)out_size;

    static_assert(sizeof(Smem) <= 232448, "smem over sm_103a opt-in limit");
    cudaFuncSetAttribute(lstm_persistent_kernel,
                         cudaFuncAttributeMaxDynamicSharedMemorySize,
                         (int)sizeof(Smem));
    lstm_persistent_kernel<<<NCTA, NTHR, sizeof(Smem)>>>(
        x, Wih1, Whh1, bih1, bhh1, Wih2, Whh2, bih2, bhh2, Wlin, blin, out);
}